// round 10
// baseline (speedup 1.0000x reference)
#include <cuda_runtime.h>
#include <cstddef>

// Problem constants (bigram trie, fixed shapes from reference)
#define V_  32768
#define C_  32
#define B_  32
#define K_  (V_ * C_)        // 1048576 bigram nodes
#define X_  (K_ + 1)         // pointers length
#define G_  V_               // unigram count
#define U_  (V_ + 1)         // first bigram node index

// Fused fill + sparse override, max-parallelism layout:
//  - grid = 1024 blocks (32 rows x 32 v-chunks), 256 threads, 1 float4/thread
//  - speculative hist loads: all S=4 candidates issued in parallel with idx,
//    collapsing the idx->hist dependence to a single load latency + select
//  - override operands (pointers/ids/logs[node]) prefetched BEFORE the barrier
//  - post-barrier tail = single predicated scalar store
__global__ void __launch_bounds__(256) llm_fused_kernel(
    const int* __restrict__ hist,
    const int* __restrict__ idx,
    const int* __restrict__ pointers,
    const int* __restrict__ ids,
    const float* __restrict__ logs,
    float* __restrict__ out,
    int S)
{
    const int blk   = blockIdx.x;          // 0..1023
    const int b     = blk >> 5;            // row (32 chunks per row)
    const int chunk = blk & 31;
    const int tid   = threadIdx.x;
    const int v0    = chunk * 1024 + tid * 4;
    float* __restrict__ row = out + (size_t)b * V_;

    // All level-0 loads issued back-to-back (independent, overlap fully).
    const float4 lv   = *reinterpret_cast<const float4*>(logs + v0);
    const int    idxv = __ldg(idx);

    int h;
    if (S == 4) {
        // Speculative: 4 hist candidates in flight concurrently with idx.
        const int a0 = __ldg(hist + 0 * B_ + b);
        const int a1 = __ldg(hist + 1 * B_ + b);
        const int a2 = __ldg(hist + 2 * B_ + b);
        const int a3 = __ldg(hist + 3 * B_ + b);
        const int sel = idxv - 1;
        h = (sel == 0) ? a0 : (sel == 1) ? a1 : (sel == 2) ? a2 : a3;
    } else {
        h = __ldg(hist + (idxv - 1) * B_ + b);
    }

    // Level-1 loads (mutually independent): backoff + override pointers.
    const float backoff = __ldg(logs + (size_t)X_ + G_ + h);

    bool  ov_do  = false;
    int   ov_tok = 0;
    float ov_lp  = 0.0f;
    if (tid < C_) {
        const int off = __ldg(pointers + h);
        const int nc  = __ldg(pointers + h + 1) - off + 1;
        if (tid < nc) {
            const int node = h + off + tid;           // bigram node id
            ov_tok = __ldg(ids + (node - U_));        // child token id
            ov_lp  = __ldg(logs + node);              // bigram log-prob
            ov_do  = (ov_tok >> 10) == chunk;         // in this block's window
        }
    }

    // Fill store.
    float4 o;
    o.x = backoff + lv.x;
    o.y = backoff + lv.y;
    o.z = backoff + lv.z;
    o.w = backoff + lv.w;
    *reinterpret_cast<float4*>(row + v0) = o;

    // Order fill stores before overrides within the block; override operands
    // are already in registers, so the post-barrier tail is one STG.
    __syncthreads();

    if (ov_do)
        row[ov_tok] = ov_lp;
}

extern "C" void kernel_launch(void* const* d_in, const int* in_sizes, int n_in,
                              void* d_out, int out_size)
{
    const int*   hist     = (const int*)d_in[0];   // (S, B) int32
    const int*   idx      = (const int*)d_in[1];   // scalar int32
    const int*   pointers = (const int*)d_in[2];   // (X,) int32
    const int*   ids      = (const int*)d_in[3];   // (K,) int32
    const float* logs     = (const float*)d_in[4]; // (L,) float32
    float*       out      = (float*)d_out;         // (B, V) float32

    const int S = in_sizes[0] / B_;                // history length (4)
    (void)n_in; (void)out_size;

    llm_fused_kernel<<<(B_ * V_) / (256 * 4), 256>>>(hist, idx, pointers, ids, logs, out, S);
}

// round 11
// speedup vs baseline: 1.0435x; 1.0435x over previous
#include <cuda_runtime.h>
#include <cstddef>

// Problem constants (bigram trie, fixed shapes from reference)
#define V_  32768
#define C_  32
#define B_  32
#define K_  (V_ * C_)        // 1048576 bigram nodes
#define X_  (K_ + 1)         // pointers length
#define G_  V_               // unigram count
#define U_  (V_ + 1)         // first bigram node index

// Fused fill + sparse override, warp-specialized uniforms:
//  - grid = 1024 blocks (32 rows x 32 v-chunks), 256 threads, 1 float4/thread
//  - warp 0 alone walks the dependent chain (idx -> h -> backoff/pointers ->
//    ids/logs[node]) and broadcasts backoff via smem; warps 1..7 issue only
//    their logs[v] float4 load. Total LDG issue count drops ~4x vs. R8.
//  - override operands live in warp-0 registers; post-fill tail = 1 predicated STG
__global__ void __launch_bounds__(256) llm_fused_kernel(
    const int* __restrict__ hist,
    const int* __restrict__ idx,
    const int* __restrict__ pointers,
    const int* __restrict__ ids,
    const float* __restrict__ logs,
    float* __restrict__ out)
{
    __shared__ float s_back;

    const int blk   = blockIdx.x;          // 0..1023
    const int b     = blk >> 5;            // row (32 chunks per row)
    const int chunk = blk & 31;
    const int tid   = threadIdx.x;
    const int v0    = chunk * 1024 + tid * 4;
    float* __restrict__ row = out + (size_t)b * V_;

    // Every thread: its own fill data, issued immediately.
    const float4 lv = *reinterpret_cast<const float4*>(logs + v0);

    // Warp 0: uniform chain + override prefetch. Other warps skip straight
    // to the barrier (their only load is already in flight).
    bool  ov_do  = false;
    int   ov_tok = 0;
    float ov_lp  = 0.0f;
    if (tid < 32) {
        const int h = __ldg(hist + (__ldg(idx) - 1) * B_ + b);
        const int off = __ldg(pointers + h);
        const int nc  = __ldg(pointers + h + 1) - off + 1;
        if (tid == 0)
            s_back = __ldg(logs + (size_t)X_ + G_ + h);
        if (tid < nc) {
            const int node = h + off + tid;           // bigram node id
            ov_tok = __ldg(ids + (node - U_));        // child token id
            ov_lp  = __ldg(logs + node);              // bigram log-prob
            ov_do  = (ov_tok >> 10) == chunk;         // in this block's window
        }
    }

    __syncthreads();   // s_back ready

    const float backoff = s_back;
    float4 o;
    o.x = backoff + lv.x;
    o.y = backoff + lv.y;
    o.z = backoff + lv.z;
    o.w = backoff + lv.w;
    *reinterpret_cast<float4*>(row + v0) = o;

    __syncthreads();   // fill stores ordered before overrides

    if (ov_do)
        row[ov_tok] = ov_lp;
}

extern "C" void kernel_launch(void* const* d_in, const int* in_sizes, int n_in,
                              void* d_out, int out_size)
{
    const int*   hist     = (const int*)d_in[0];   // (S, B) int32
    const int*   idx      = (const int*)d_in[1];   // scalar int32
    const int*   pointers = (const int*)d_in[2];   // (X,) int32
    const int*   ids      = (const int*)d_in[3];   // (K,) int32
    const float* logs     = (const float*)d_in[4]; // (L,) float32
    float*       out      = (float*)d_out;         // (B, V) float32

    (void)in_sizes; (void)n_in; (void)out_size;

    llm_fused_kernel<<<(B_ * V_) / (256 * 4), 256>>>(hist, idx, pointers, ids, logs, out);
}